// round 1
// baseline (speedup 1.0000x reference)
#include <cuda_runtime.h>

#define SEQ 25
#define BATCH 4096
#define INPUT 500
#define HIDDEN 64
#define GATES 256            // 4*HIDDEN
#define NLAYERS 25
#define OUTDIM 10

#define OFF_HN (SEQ*OUTDIM)                         // 250
#define OFF_CN (OFF_HN + NLAYERS*BATCH*HIDDEN)      // 6,553,850

typedef unsigned long long ull;

// ---------------- scratch (static device allocations; no cudaMalloc) --------
__device__ float g_xp0[(size_t)SEQ*BATCH*GATES];            // 100 MB: layer-0 input projection (+biases)
__device__ float g_hsA[(size_t)SEQ*BATCH*HIDDEN];           // 26 MB ping
__device__ float g_hsB[(size_t)SEQ*BATCH*HIDDEN];           // 26 MB pong
__device__ float g_W0t[INPUT*GATES];                        // W_ih0 transposed [k][g]
__device__ float g_Whh0t[HIDDEN*GATES];                     // W_hh0 transposed [k][g]
__device__ float g_WcatT[(size_t)(NLAYERS-1)*2*HIDDEN*GATES]; // per layer: [k(128)][g] = [Wih;Whh]^T

// ---------------- f32x2 packed math helpers (sm_100+) -----------------------
__device__ __forceinline__ ull fma2(ull a, ull b, ull c){
    ull d;
    asm("fma.rn.f32x2 %0, %1, %2, %3;" : "=l"(d) : "l"(a), "l"(b), "l"(c));
    return d;
}
__device__ __forceinline__ ull dup2(float x){
    ull d; unsigned u = __float_as_uint(x);
    asm("mov.b64 %0, {%1, %1};" : "=l"(d) : "r"(u));
    return d;
}
__device__ __forceinline__ float2 unpack2(ull v){
    float2 r;
    asm("mov.b64 {%0, %1}, %2;" : "=f"(r.x), "=f"(r.y) : "l"(v));
    return r;
}
__device__ __forceinline__ float sigm(float x){
    return __fdividef(1.f, 1.f + __expf(-x));
}
__device__ __forceinline__ float tanh_f(float x){
    float a = __expf(fminf(2.f*x, 80.f));   // large +x safe; -x -> a=0 -> -1
    return __fdividef(a - 1.f, a + 1.f);
}

// ---------------- weight transposes (one-shot, tiny) ------------------------
__global__ void transpose_w0(const float* __restrict__ W){ // W [GATES][INPUT]
    int idx = blockIdx.x*blockDim.x + threadIdx.x;
    if (idx < INPUT*GATES){
        int k = idx / GATES, g = idx % GATES;
        g_W0t[idx] = W[g*INPUT + k];
    }
}
__global__ void transpose_whh0(const float* __restrict__ W){ // W [GATES][HIDDEN]
    int idx = blockIdx.x*blockDim.x + threadIdx.x;
    if (idx < HIDDEN*GATES){
        int k = idx / GATES, g = idx % GATES;
        g_Whh0t[idx] = W[g*HIDDEN + k];
    }
}
__global__ void transpose_wr(const float* __restrict__ Wih, const float* __restrict__ Whh){
    int idx = blockIdx.x*blockDim.x + threadIdx.x;
    const int tot = (NLAYERS-1)*2*HIDDEN*GATES;
    if (idx < tot){
        int g = idx % GATES;
        int k = (idx / GATES) % (2*HIDDEN);
        int l = idx / (GATES*2*HIDDEN);
        float v = (k < HIDDEN) ? Wih[((size_t)l*GATES + g)*HIDDEN + k]
                               : Whh[((size_t)l*GATES + g)*HIDDEN + (k-HIDDEN)];
        g_WcatT[idx] = v;
    }
}

// ---------------- layer-0 input projection: [102400,500] x [500,256] --------
#define P0_ROWS 64
#define P0_KC 10
__global__ void __launch_bounds__(256) proj0_kernel(const float* __restrict__ x,
                                                    const float* __restrict__ bih,
                                                    const float* __restrict__ bhh){
    __shared__ __align__(16) float xs[P0_ROWS][P0_KC+2];   // stride 12: conflict-free across rg
    __shared__ __align__(16) float ws[P0_KC][GATES];
    const int tid = threadIdx.x;
    const int row0 = blockIdx.x * P0_ROWS;
    const int rg = tid & 7, cg = tid >> 3;
    const int c0 = cg * 8;

    ull acc[8][4];
    #pragma unroll
    for (int i=0;i<8;i++){
        #pragma unroll
        for (int j=0;j<4;j++) acc[i][j] = 0ULL;
    }

    for (int k0 = 0; k0 < INPUT; k0 += P0_KC){
        for (int idx = tid; idx < P0_ROWS*P0_KC; idx += 256){
            int r = idx / P0_KC, kk = idx % P0_KC;
            xs[r][kk] = x[(size_t)(row0 + r)*INPUT + k0 + kk];
        }
        for (int idx = tid; idx < P0_KC*GATES; idx += 256){
            int kk = idx / GATES, c = idx % GATES;
            ws[kk][c] = g_W0t[(k0 + kk)*GATES + c];
        }
        __syncthreads();
        #pragma unroll
        for (int kk = 0; kk < P0_KC; kk++){
            ulonglong2 wa = *(const ulonglong2*)&ws[kk][c0];
            ulonglong2 wb = *(const ulonglong2*)&ws[kk][c0+4];
            #pragma unroll
            for (int i=0;i<8;i++){
                ull xd = dup2(xs[rg + 8*i][kk]);
                acc[i][0] = fma2(xd, wa.x, acc[i][0]);
                acc[i][1] = fma2(xd, wa.y, acc[i][1]);
                acc[i][2] = fma2(xd, wb.x, acc[i][2]);
                acc[i][3] = fma2(xd, wb.y, acc[i][3]);
            }
        }
        __syncthreads();
    }
    float b[8];
    #pragma unroll
    for (int j=0;j<8;j++) b[j] = bih[c0+j] + bhh[c0+j];
    #pragma unroll
    for (int i=0;i<8;i++){
        size_t r = (size_t)(row0 + rg + 8*i);
        float* dst = &g_xp0[r*GATES + c0];
        float2 p0 = unpack2(acc[i][0]), p1 = unpack2(acc[i][1]);
        float2 p2 = unpack2(acc[i][2]), p3 = unpack2(acc[i][3]);
        *(float4*)(dst)   = make_float4(p0.x+b[0], p0.y+b[1], p1.x+b[2], p1.y+b[3]);
        *(float4*)(dst+4) = make_float4(p2.x+b[4], p2.y+b[5], p3.x+b[6], p3.y+b[7]);
    }
}

// ---------------- per-layer persistent LSTM kernel ---------------------------
// FIRST=true : layer 0. Preactivations read from g_xp0 (K=64 recurrence only).
// FIRST=false: layers 1..24. On-the-fly input proj fused: K=128 over [x|h].
// Grid: 128 CTAs x 256 threads; each CTA owns 32 batch rows for all 25 steps.
template<bool FIRST>
__global__ void __launch_bounds__(256) lstm_layer_kernel(int pp, int layer,
        const float* __restrict__ bihR, const float* __restrict__ bhhR,
        float* __restrict__ out){
    constexpr int KW = FIRST ? HIDDEN : 2*HIDDEN;
    constexpr int XS = FIRST ? 68 : 132;   // padded strides: conflict-free LDS across row groups
    constexpr int CS = 68;
    constexpr int GS = 260;
    extern __shared__ float sm[];
    float* sWt = sm;                   // [KW][GATES]  (k-major, pre-transposed)
    float* sX  = sWt + KW*GATES;       // [32][XS] : FIRST: h state. else: [x(0:64)|h(64:128)]
    float* sC  = sX  + 32*XS;          // [32][CS] : c state
    float* sG  = sC  + 32*CS;          // [32][GS] : gate preactivations
    float* sB  = sG  + 32*GS;          // [GATES]  : bias (unused if FIRST)

    const int tid   = threadIdx.x;
    const int brow0 = blockIdx.x * 32;
    const int rg = tid & 7, cg = tid >> 3;
    const int r0 = rg * 4, c0 = cg * 8;

    const float* hs_in = nullptr;
    float* hs_out;
    if (FIRST){ hs_out = g_hsA; }
    else { hs_in = pp ? g_hsB : g_hsA; hs_out = pp ? g_hsA : g_hsB; }

    // prologue: weights, bias, zero states
    {
        const float* wsrc = FIRST ? g_Whh0t : &g_WcatT[(size_t)(layer-1)*KW*GATES];
        for (int idx = tid*4; idx < KW*GATES; idx += 256*4)
            *(float4*)&sWt[idx] = *(const float4*)&wsrc[idx];
        if (!FIRST){
            sB[tid] = bihR[(size_t)(layer-1)*GATES + tid] + bhhR[(size_t)(layer-1)*GATES + tid];
        }
        for (int idx = tid; idx < 32*XS; idx += 256) sX[idx] = 0.f;
        for (int idx = tid; idx < 32*CS; idx += 256) sC[idx] = 0.f;
    }
    __syncthreads();

    const int hoff = FIRST ? 0 : HIDDEN;

    #pragma unroll 1
    for (int t = 0; t < SEQ; t++){
        if (!FIRST){
            // stage this timestep's input (prev layer h) into sX[:,0:64]
            for (int idx = tid*4; idx < 32*HIDDEN; idx += 1024){
                int r = idx >> 6, k = idx & 63;
                *(float4*)&sX[r*XS + k] =
                    *(const float4*)&hs_in[((size_t)t*BATCH + brow0 + r)*HIDDEN + k];
            }
        }
        __syncthreads();

        // -------- gate GEMM: g[32][256] += [x|h] @ Wcat^T, f32x2 packed ------
        ull acc[4][4];
        if (FIRST){
            #pragma unroll
            for (int i=0;i<4;i++){
                const float* src = &g_xp0[((size_t)t*BATCH + brow0 + r0 + i)*GATES + c0];
                ulonglong2 a  = *(const ulonglong2*)src;
                ulonglong2 b2 = *(const ulonglong2*)(src+4);
                acc[i][0]=a.x; acc[i][1]=a.y; acc[i][2]=b2.x; acc[i][3]=b2.y;
            }
        } else {
            #pragma unroll
            for (int i=0;i<4;i++){
                #pragma unroll
                for (int j=0;j<4;j++) acc[i][j] = 0ULL;
            }
        }
        #pragma unroll 8
        for (int k = 0; k < KW; k++){
            ulonglong2 wa = *(const ulonglong2*)&sWt[k*GATES + c0];
            ulonglong2 wb = *(const ulonglong2*)&sWt[k*GATES + c0 + 4];
            #pragma unroll
            for (int i=0;i<4;i++){
                ull xd = dup2(sX[(r0+i)*XS + k]);
                acc[i][0] = fma2(xd, wa.x, acc[i][0]);
                acc[i][1] = fma2(xd, wa.y, acc[i][1]);
                acc[i][2] = fma2(xd, wb.x, acc[i][2]);
                acc[i][3] = fma2(xd, wb.y, acc[i][3]);
            }
        }
        #pragma unroll
        for (int i=0;i<4;i++){
            #pragma unroll
            for (int j=0;j<4;j++){
                float2 p = unpack2(acc[i][j]);
                if (!FIRST){ p.x += sB[c0+2*j]; p.y += sB[c0+2*j+1]; }
                *(float2*)&sG[(r0+i)*GS + c0 + 2*j] = p;
            }
        }
        __syncthreads();

        // -------- elementwise gates: each thread: 1 row x 8 hidden units -----
        {
            const int row = tid >> 3;
            const int jb  = (tid & 7) * 8;
            float* gr = &sG[row*GS];
            float* cr = &sC[row*CS];
            float hv[8], cv[8];
            #pragma unroll
            for (int jj=0;jj<8;jj++){
                int j = jb + jj;
                float ig = gr[j], fg = gr[HIDDEN + j], gg = gr[2*HIDDEN + j], og = gr[3*HIDDEN + j];
                float c = sigm(fg)*cr[j] + sigm(ig)*tanh_f(gg);
                float h = sigm(og)*tanh_f(c);
                cr[j] = c;
                sX[row*XS + hoff + j] = h;
                hv[jj] = h; cv[jj] = c;
            }
            float4* dh = (float4*)&hs_out[((size_t)t*BATCH + brow0 + row)*HIDDEN + jb];
            dh[0] = make_float4(hv[0],hv[1],hv[2],hv[3]);
            dh[1] = make_float4(hv[4],hv[5],hv[6],hv[7]);
            if (t == SEQ-1){
                size_t base = (size_t)layer*BATCH*HIDDEN + (size_t)(brow0+row)*HIDDEN + jb;
                #pragma unroll
                for (int jj=0;jj<8;jj++){
                    out[OFF_HN + base + jj] = hv[jj];
                    out[OFF_CN + base + jj] = cv[jj];
                }
            }
        }
        __syncthreads();
    }
}

// ---------------- final tiny linear: hs[:, B-1, :] @ W_lin^T + b ------------
__global__ void final_kernel(const float* __restrict__ Wlin, const float* __restrict__ blin,
                             float* __restrict__ out){
    int tid = threadIdx.x;
    if (tid < SEQ*OUTDIM){
        int t = tid / OUTDIM, o = tid % OUTDIM;
        const float* h = &g_hsA[((size_t)t*BATCH + (BATCH-1))*HIDDEN];
        float acc = blin[o];
        #pragma unroll
        for (int j=0;j<HIDDEN;j++) acc = fmaf(h[j], Wlin[o*HIDDEN + j], acc);
        out[t*OUTDIM + o] = acc;
    }
}

// ---------------- host ------------------------------------------------------
extern "C" void kernel_launch(void* const* d_in, const int* in_sizes, int n_in,
                              void* d_out, int out_size){
    const float* x     = (const float*)d_in[0];
    const float* Wih0  = (const float*)d_in[1];
    const float* Whh0  = (const float*)d_in[2];
    const float* bih0  = (const float*)d_in[3];
    const float* bhh0  = (const float*)d_in[4];
    const float* WihR  = (const float*)d_in[5];
    const float* WhhR  = (const float*)d_in[6];
    const float* bihR  = (const float*)d_in[7];
    const float* bhhR  = (const float*)d_in[8];
    const float* Wlin  = (const float*)d_in[9];
    const float* blin  = (const float*)d_in[10];
    float* out = (float*)d_out;

    const int SMEM_FIRST = (HIDDEN*GATES + 32*68 + 32*68 + 32*260) * 4;              // ~116 KB
    const int SMEM_REST  = (2*HIDDEN*GATES + 32*132 + 32*68 + 32*260 + GATES) * 4;   // ~191 KB
    cudaFuncSetAttribute(lstm_layer_kernel<true>,  cudaFuncAttributeMaxDynamicSharedMemorySize, SMEM_FIRST);
    cudaFuncSetAttribute(lstm_layer_kernel<false>, cudaFuncAttributeMaxDynamicSharedMemorySize, SMEM_REST);

    transpose_w0  <<<(INPUT*GATES + 255)/256, 256>>>(Wih0);
    transpose_whh0<<<(HIDDEN*GATES + 255)/256, 256>>>(Whh0);
    transpose_wr  <<<((NLAYERS-1)*2*HIDDEN*GATES + 255)/256, 256>>>(WihR, WhhR);

    proj0_kernel<<<(SEQ*BATCH)/P0_ROWS, 256>>>(x, bih0, bhh0);

    lstm_layer_kernel<true><<<BATCH/32, 256, SMEM_FIRST>>>(0, 0, nullptr, nullptr, out);
    for (int l = 1; l < NLAYERS; l++){
        int pp = (l - 1) & 1;
        lstm_layer_kernel<false><<<BATCH/32, 256, SMEM_REST>>>(pp, l, bihR, bhhR, out);
    }
    final_kernel<<<1, 256>>>(Wlin, blin, out);
}

// round 4
// speedup vs baseline: 1.8588x; 1.8588x over previous
#include <cuda_runtime.h>

#define SEQ 25
#define BATCH 4096
#define INPUT 500
#define HIDDEN 64
#define GATES 256            // 4*HIDDEN
#define NLAYERS 25
#define OUTDIM 10

#define OFF_HN (SEQ*OUTDIM)                         // 250
#define OFF_CN (OFF_HN + NLAYERS*BATCH*HIDDEN)

typedef unsigned long long ull;

__host__ __device__ constexpr int align4(int x){ return (x + 3) & ~3; }

// ---------------- scratch (static device allocations) -----------------------
__device__ float g_xp0[(size_t)SEQ*BATCH*GATES];              // layer-0 input proj (+biases), PERMUTED cols
__device__ float g_hsA[(size_t)SEQ*BATCH*HIDDEN];
__device__ float g_hsB[(size_t)SEQ*BATCH*HIDDEN];
__device__ float g_W0t[INPUT*GATES];                          // [k][cp] permuted
__device__ float g_Whh0t[HIDDEN*GATES];                       // [k][cp] permuted
__device__ float g_WcatT[(size_t)(NLAYERS-1)*2*HIDDEN*GATES]; // [l][k(128)][cp] permuted

// permuted column cp = j*4 + gate  ->  natural torch col = gate*64 + j
__host__ __device__ __forceinline__ int natcol(int cp){ return (cp & 3)*64 + (cp >> 2); }

// ---------------- f32x2 packed math helpers ---------------------------------
__device__ __forceinline__ ull fma2(ull a, ull b, ull c){
    ull d; asm("fma.rn.f32x2 %0, %1, %2, %3;" : "=l"(d) : "l"(a), "l"(b), "l"(c)); return d;
}
__device__ __forceinline__ ull dup2(float x){
    ull d; unsigned u = __float_as_uint(x);
    asm("mov.b64 %0, {%1, %1};" : "=l"(d) : "r"(u)); return d;
}
__device__ __forceinline__ ull pack2(float a, float b){
    ull d; asm("mov.b64 %0, {%1, %2};" : "=l"(d) : "f"(a), "f"(b)); return d;
}
__device__ __forceinline__ float2 unpack2(ull v){
    float2 r; asm("mov.b64 {%0, %1}, %2;" : "=f"(r.x), "=f"(r.y) : "l"(v)); return r;
}
__device__ __forceinline__ float sigm(float x){
    return __fdividef(1.f, 1.f + __expf(-x));
}
__device__ __forceinline__ float tanh_f(float x){
    float a = __expf(fminf(2.f*x, 80.f));
    return __fdividef(a - 1.f, a + 1.f);
}

// ---------------- weight transposes (one-shot, permuted columns) ------------
__global__ void transpose_w0(const float* __restrict__ W){ // W [GATES][INPUT]
    int idx = blockIdx.x*blockDim.x + threadIdx.x;
    if (idx < INPUT*GATES){
        int k = idx / GATES, cp = idx % GATES;
        g_W0t[idx] = W[natcol(cp)*INPUT + k];
    }
}
__global__ void transpose_whh0(const float* __restrict__ W){ // W [GATES][HIDDEN]
    int idx = blockIdx.x*blockDim.x + threadIdx.x;
    if (idx < HIDDEN*GATES){
        int k = idx / GATES, cp = idx % GATES;
        g_Whh0t[idx] = W[natcol(cp)*HIDDEN + k];
    }
}
__global__ void transpose_wr(const float* __restrict__ Wih, const float* __restrict__ Whh){
    int idx = blockIdx.x*blockDim.x + threadIdx.x;
    const int tot = (NLAYERS-1)*2*HIDDEN*GATES;
    if (idx < tot){
        int cp = idx % GATES;
        int k  = (idx / GATES) % (2*HIDDEN);
        int l  = idx / (GATES*2*HIDDEN);
        int nc = natcol(cp);
        float v = (k < HIDDEN) ? Wih[((size_t)l*GATES + nc)*HIDDEN + k]
                               : Whh[((size_t)l*GATES + nc)*HIDDEN + (k-HIDDEN)];
        g_WcatT[idx] = v;
    }
}

// ---------------- layer-0 input projection (writes permuted cols) -----------
#define P0_ROWS 64
#define P0_KC 10
__global__ void __launch_bounds__(256) proj0_kernel(const float* __restrict__ x,
                                                    const float* __restrict__ bih,
                                                    const float* __restrict__ bhh){
    __shared__ __align__(16) float xs[P0_ROWS][P0_KC+2];
    __shared__ __align__(16) float ws[P0_KC][GATES];
    const int tid = threadIdx.x;
    const int row0 = blockIdx.x * P0_ROWS;
    const int rg = tid & 7, cg = tid >> 3;
    const int c0 = cg * 8;

    ull acc[8][4];
    #pragma unroll
    for (int i=0;i<8;i++){
        #pragma unroll
        for (int j=0;j<4;j++) acc[i][j] = 0ULL;
    }

    for (int k0 = 0; k0 < INPUT; k0 += P0_KC){
        for (int idx = tid; idx < P0_ROWS*P0_KC; idx += 256){
            int r = idx / P0_KC, kk = idx % P0_KC;
            xs[r][kk] = x[(size_t)(row0 + r)*INPUT + k0 + kk];
        }
        for (int idx = tid; idx < P0_KC*GATES; idx += 256){
            int kk = idx / GATES, c = idx % GATES;
            ws[kk][c] = g_W0t[(k0 + kk)*GATES + c];
        }
        __syncthreads();
        #pragma unroll
        for (int kk = 0; kk < P0_KC; kk++){
            ulonglong2 wa = *(const ulonglong2*)&ws[kk][c0];
            ulonglong2 wb = *(const ulonglong2*)&ws[kk][c0+4];
            #pragma unroll
            for (int i=0;i<8;i++){
                ull xd = dup2(xs[rg + 8*i][kk]);
                acc[i][0] = fma2(xd, wa.x, acc[i][0]);
                acc[i][1] = fma2(xd, wa.y, acc[i][1]);
                acc[i][2] = fma2(xd, wb.x, acc[i][2]);
                acc[i][3] = fma2(xd, wb.y, acc[i][3]);
            }
        }
        __syncthreads();
    }
    float b[8];
    #pragma unroll
    for (int j=0;j<8;j++){ int nc = natcol(c0+j); b[j] = bih[nc] + bhh[nc]; }
    #pragma unroll
    for (int i=0;i<8;i++){
        size_t r = (size_t)(row0 + rg + 8*i);
        float* dst = &g_xp0[r*GATES + c0];
        float2 p0 = unpack2(acc[i][0]), p1 = unpack2(acc[i][1]);
        float2 p2 = unpack2(acc[i][2]), p3 = unpack2(acc[i][3]);
        *(float4*)(dst)   = make_float4(p0.x+b[0], p0.y+b[1], p1.x+b[2], p1.y+b[3]);
        *(float4*)(dst+4) = make_float4(p2.x+b[4], p2.y+b[5], p3.x+b[6], p3.y+b[7]);
    }
}

// ---------------- per-layer persistent LSTM kernel ---------------------------
// Skewed sX layout: addr(row,k) = row*RS + 4*(row>>2) + k  -> conflict-free
// broadcasts over the warp's 8 rows, 16B-aligned bases.
template<bool FIRST>
__global__ void __launch_bounds__(256) lstm_layer_kernel(int pp, int layer,
        const float* __restrict__ bihR, const float* __restrict__ bhhR,
        float* __restrict__ out){
    constexpr int KW   = FIRST ? HIDDEN : 2*HIDDEN;
    constexpr int RS   = FIRST ? 72 : 136;
    constexpr int HOFF = FIRST ? 0 : HIDDEN;
    constexpr int BUFW = align4(31*RS + 28 + (KW-1) + 8);   // multiple of 4 -> buf1 stays 16B-aligned
    extern __shared__ float sm[];
    float* sW   = sm;                 // [KW][256] permuted, k-major
    float* buf0 = sW + KW*GATES;
    float* buf1 = buf0 + BUFW;

    const int tid   = threadIdx.x;
    const int brow0 = blockIdx.x * 32;
    const int rg = tid & 7, cg = tid >> 3;
    const int r0 = rg * 4, c0 = cg * 8;
    const int u0 = 2 * cg;            // this thread's 2 hidden units

    const float* hs_in = nullptr;
    float* hs_out;
    if (FIRST){ hs_out = g_hsA; }
    else { hs_in = pp ? g_hsB : g_hsA; hs_out = pp ? g_hsA : g_hsB; }

    // ---- prologue ----
    {
        const float* wsrc = FIRST ? g_Whh0t : &g_WcatT[(size_t)(layer-1)*KW*GATES];
        for (int idx = tid*4; idx < KW*GATES; idx += 256*4)
            *(float4*)&sW[idx] = *(const float4*)&wsrc[idx];
        for (int idx = tid; idx < BUFW; idx += 256) buf0[idx] = 0.f;
    }
    ull bb[4];
    if (!FIRST){
        float b[8];
        #pragma unroll
        for (int j=0;j<8;j++){
            int nc = natcol(c0+j);
            b[j] = bihR[(size_t)(layer-1)*GATES + nc] + bhhR[(size_t)(layer-1)*GATES + nc];
        }
        #pragma unroll
        for (int j=0;j<4;j++) bb[j] = pack2(b[2*j], b[2*j+1]);
    }
    __syncthreads();
    if (!FIRST){   // stage x(0)
        int prow = tid >> 3, pks = (tid & 7)*8;
        const float* src = &hs_in[((size_t)0*BATCH + brow0 + prow)*HIDDEN + pks];
        float4 a = *(const float4*)src, b4 = *(const float4*)(src+4);
        float* d = &buf0[prow*RS + 4*(prow>>2) + pks];
        *(float4*)d = a; *(float4*)(d+4) = b4;
    }
    float cc[8];
    #pragma unroll
    for (int i=0;i<8;i++) cc[i] = 0.f;
    __syncthreads();

    float* cur = buf0;
    float* nxt = buf1;
    int base0 = r0*RS + 4*(r0>>2);            // r0 multiple of 4 -> rows r0..r0+3 share (row>>2)
    int rb[4];
    #pragma unroll
    for (int i=0;i<4;i++) rb[i] = base0 + i*RS;

    #pragma unroll 1
    for (int t = 0; t < SEQ; t++){
        // prefetch next-step x into registers (hidden under GEMM)
        float4 xp0r, xp1r;
        const int prow = tid >> 3, pks = (tid & 7)*8;
        if (!FIRST && t+1 < SEQ){
            const float* src = &hs_in[((size_t)(t+1)*BATCH + brow0 + prow)*HIDDEN + pks];
            xp0r = *(const float4*)src; xp1r = *(const float4*)(src+4);
        }

        // ---- acc init ----
        ull acc[4][4];
        if (FIRST){
            #pragma unroll
            for (int i=0;i<4;i++){
                const float* s = &g_xp0[((size_t)t*BATCH + brow0 + r0 + i)*GATES + c0];
                ulonglong2 a  = *(const ulonglong2*)s;
                ulonglong2 b2 = *(const ulonglong2*)(s+4);
                acc[i][0]=a.x; acc[i][1]=a.y; acc[i][2]=b2.x; acc[i][3]=b2.y;
            }
        } else {
            #pragma unroll
            for (int i=0;i<4;i++){ acc[i][0]=bb[0]; acc[i][1]=bb[1]; acc[i][2]=bb[2]; acc[i][3]=bb[3]; }
        }

        // ---- gate GEMM ----
        #pragma unroll 8
        for (int k = 0; k < KW; k++){
            ulonglong2 wa = *(const ulonglong2*)&sW[k*GATES + c0];
            ulonglong2 wb = *(const ulonglong2*)&sW[k*GATES + c0 + 4];
            #pragma unroll
            for (int i=0;i<4;i++){
                ull xd = dup2(cur[rb[i] + k]);
                acc[i][0] = fma2(xd, wa.x, acc[i][0]);
                acc[i][1] = fma2(xd, wa.y, acc[i][1]);
                acc[i][2] = fma2(xd, wb.x, acc[i][2]);
                acc[i][3] = fma2(xd, wb.y, acc[i][3]);
            }
        }

        // ---- elementwise in registers: cols are (i,f,g,o) x 2 units --------
        #pragma unroll
        for (int i=0;i<4;i++){
            float2 if0 = unpack2(acc[i][0]);   // (i, f) unit u0
            float2 go0 = unpack2(acc[i][1]);   // (g, o) unit u0
            float2 if1 = unpack2(acc[i][2]);   // (i, f) unit u0+1
            float2 go1 = unpack2(acc[i][3]);   // (g, o) unit u0+1
            float cn0 = sigm(if0.y)*cc[2*i]   + sigm(if0.x)*tanh_f(go0.x);
            float cn1 = sigm(if1.y)*cc[2*i+1] + sigm(if1.x)*tanh_f(go1.x);
            float h0 = sigm(go0.y)*tanh_f(cn0);
            float h1 = sigm(go1.y)*tanh_f(cn1);
            cc[2*i] = cn0; cc[2*i+1] = cn1;

            // h -> global (next layer input)
            *(float2*)&hs_out[((size_t)t*BATCH + brow0 + r0 + i)*HIDDEN + u0] = make_float2(h0, h1);
            // h -> next-step smem buffer
            *(float2*)&nxt[rb[i] + HOFF + u0] = make_float2(h0, h1);

            if (t == SEQ-1){
                size_t ob = (size_t)layer*BATCH*HIDDEN + (size_t)(brow0 + r0 + i)*HIDDEN + u0;
                out[OFF_HN + ob]     = h0;  out[OFF_HN + ob + 1] = h1;
                out[OFF_CN + ob]     = cn0; out[OFF_CN + ob + 1] = cn1;
            }
        }

        // ---- store staged x(t+1) ----
        if (!FIRST && t+1 < SEQ){
            float* d = &nxt[prow*RS + 4*(prow>>2) + pks];
            *(float4*)d = xp0r; *(float4*)(d+4) = xp1r;
        }
        __syncthreads();
        float* tmp = cur; cur = nxt; nxt = tmp;
    }
}

// ---------------- final tiny linear ------------------------------------------
__global__ void final_kernel(const float* __restrict__ Wlin, const float* __restrict__ blin,
                             float* __restrict__ out){
    int tid = threadIdx.x;
    if (tid < SEQ*OUTDIM){
        int t = tid / OUTDIM, o = tid % OUTDIM;
        const float* h = &g_hsA[((size_t)t*BATCH + (BATCH-1))*HIDDEN];
        float acc = blin[o];
        #pragma unroll
        for (int j=0;j<HIDDEN;j++) acc = fmaf(h[j], Wlin[o*HIDDEN + j], acc);
        out[t*OUTDIM + o] = acc;
    }
}

// ---------------- host ------------------------------------------------------
extern "C" void kernel_launch(void* const* d_in, const int* in_sizes, int n_in,
                              void* d_out, int out_size){
    const float* x     = (const float*)d_in[0];
    const float* Wih0  = (const float*)d_in[1];
    const float* Whh0  = (const float*)d_in[2];
    const float* bih0  = (const float*)d_in[3];
    const float* bhh0  = (const float*)d_in[4];
    const float* WihR  = (const float*)d_in[5];
    const float* WhhR  = (const float*)d_in[6];
    const float* bihR  = (const float*)d_in[7];
    const float* bhhR  = (const float*)d_in[8];
    const float* Wlin  = (const float*)d_in[9];
    const float* blin  = (const float*)d_in[10];
    float* out = (float*)d_out;

    constexpr int BUFW_F = align4(31*72  + 28 + 63  + 8);
    constexpr int BUFW_R = align4(31*136 + 28 + 127 + 8);
    const int SMEM_FIRST = (HIDDEN*GATES   + 2*BUFW_F) * 4;
    const int SMEM_REST  = (2*HIDDEN*GATES + 2*BUFW_R) * 4;
    cudaFuncSetAttribute(lstm_layer_kernel<true>,  cudaFuncAttributeMaxDynamicSharedMemorySize, SMEM_FIRST);
    cudaFuncSetAttribute(lstm_layer_kernel<false>, cudaFuncAttributeMaxDynamicSharedMemorySize, SMEM_REST);

    transpose_w0  <<<(INPUT*GATES + 255)/256, 256>>>(Wih0);
    transpose_whh0<<<(HIDDEN*GATES + 255)/256, 256>>>(Whh0);
    transpose_wr  <<<((NLAYERS-1)*2*HIDDEN*GATES + 255)/256, 256>>>(WihR, WhhR);

    proj0_kernel<<<(SEQ*BATCH)/P0_ROWS, 256>>>(x, bih0, bhh0);

    lstm_layer_kernel<true><<<BATCH/32, 256, SMEM_FIRST>>>(0, 0, nullptr, nullptr, out);
    for (int l = 1; l < NLAYERS; l++){
        int pp = (l - 1) & 1;
        lstm_layer_kernel<false><<<BATCH/32, 256, SMEM_REST>>>(pp, l, bihR, bhhR, out);
    }
    final_kernel<<<1, 256>>>(Wlin, blin, out);
}